// round 6
// baseline (speedup 1.0000x reference)
#include <cuda_runtime.h>
#include <cuda_bf16.h>

// Output layout (flattened f32 concat of the reference tuple):
//   [0, 3V)                      verts_3d   (V x 3)
//   [3V, 3V + Fe)                faces cast to f32 (Fe = in_sizes[3])
//   [3V + Fe, 3V + Fe + V*D)     verts_features copy
//
// Features region: BLOCKED contiguous-chunk copy (each block owns one
// contiguous slice, streams 8KB/iteration) for DRAM row-buffer locality,
// using 256-bit ld/st when the dst slice is 32B-aligned.
// faces/verts: grid-stride tails (tiny).

__global__ void __launch_bounds__(256, 8) fused_all_kernel(
    const float* __restrict__ verts_logit,
    const float* __restrict__ verts_features,
    const float* __restrict__ boundary,
    const int*   __restrict__ faces,
    float* __restrict__ out,
    int V, int faces_elems, int feat_elems,
    int feat_mode,          // 2 = v8, 1 = v4, 0 = v4 load + scalar stores
    long long chunk)        // feat items per block (contiguous)
{
    const long long threeV = 3LL * V;
    float* __restrict__ out_faces    = out + threeV;
    float* __restrict__ out_features = out_faces + faces_elems;

    const long long Wfeat  = (feat_mode == 2) ? (feat_elems >> 3)
                                              : (feat_elems >> 2);
    const long long Wfaces = (faces_elems + 3) >> 2;

    // ---- region 1: blocked contiguous features copy ----
    {
        long long beg = (long long)blockIdx.x * chunk;
        long long end = beg + chunk;
        if (end > Wfeat) end = Wfeat;
        if (feat_mode == 2) {
            for (long long i = beg + threadIdx.x; i < end; i += blockDim.x) {
                const float* s = verts_features + (i << 3);
                float*       d = out_features   + (i << 3);
                float a0, a1, a2, a3, a4, a5, a6, a7;
                asm volatile(
                    "ld.global.nc.v8.f32 {%0,%1,%2,%3,%4,%5,%6,%7}, [%8];"
                    : "=f"(a0), "=f"(a1), "=f"(a2), "=f"(a3),
                      "=f"(a4), "=f"(a5), "=f"(a6), "=f"(a7)
                    : "l"(s));
                asm volatile(
                    "st.global.v8.f32 [%0], {%1,%2,%3,%4,%5,%6,%7,%8};"
                    :: "l"(d),
                       "f"(a0), "f"(a1), "f"(a2), "f"(a3),
                       "f"(a4), "f"(a5), "f"(a6), "f"(a7)
                    : "memory");
            }
        } else if (feat_mode == 1) {
            for (long long i = beg + threadIdx.x; i < end; i += blockDim.x) {
                const float4 v = __ldg((const float4*)verts_features + i);
                ((float4*)out_features)[i] = v;
            }
        } else {
            for (long long i = beg + threadIdx.x; i < end; i += blockDim.x) {
                const float4 v = __ldg((const float4*)verts_features + i);
                float* d = out_features + (i << 2);
                d[0] = v.x; d[1] = v.y; d[2] = v.z; d[3] = v.w;
            }
        }
    }

    // ---- region 2 + 3: grid-stride tails ----
    const long long S   = (long long)gridDim.x * blockDim.x;
    const long long tid = (long long)blockIdx.x * blockDim.x + threadIdx.x;

    for (long long j = tid; j < Wfaces; j += S) {
        const long long e = j << 2;
        if (e + 4 <= faces_elems) {
            const int4 f = __ldg((const int4*)faces + j);
            float4 o;
            o.x = (float)f.x; o.y = (float)f.y;
            o.z = (float)f.z; o.w = (float)f.w;
            ((float4*)out_faces)[j] = o;            // offset 3V %4 == 0
        } else {
            for (long long k = e; k < faces_elems; k++)
                out_faces[k] = (float)__ldg(faces + k);
        }
    }

    for (long long i = tid; i < V; i += S) {
        float x, y;
        if (i < 4) {
            x = boundary[2 * i];
            y = boundary[2 * i + 1];
        } else {
            const float2 l = __ldg((const float2*)verts_logit + i);
            x = 2.0f / (1.0f + __expf(-l.x)) - 1.0f;
            y = 2.0f / (1.0f + __expf(-l.y)) - 1.0f;
        }
        float* d = out + 3LL * i;
        d[0] = x; d[1] = y; d[2] = 1.0f;
    }
}

extern "C" void kernel_launch(void* const* d_in, const int* in_sizes, int n_in,
                              void* d_out, int out_size) {
    const float* verts_logit    = (const float*)d_in[0];   // V*2
    const float* verts_features = (const float*)d_in[1];   // V*D
    const float* boundary       = (const float*)d_in[2];   // 4*2
    const int*   faces          = (const int*)d_in[3];     // F*3 (int32)

    const int V           = in_sizes[0] / 2;
    const int feat_elems  = in_sizes[1];                   // V*128, %8 == 0
    const int faces_elems = in_sizes[3];

    const long long off = 3LL * V + faces_elems;           // dst slice offset
    int feat_mode;
    if ((off & 7) == 0)      feat_mode = 2;                // 32B aligned: v8
    else if ((off & 3) == 0) feat_mode = 1;                // 16B aligned: v4
    else                     feat_mode = 0;                // scalar stores

    const int threads = 256;
    const int blocks  = 148 * 16;                          // best known config

    const long long Wfeat = (feat_mode == 2) ? (feat_elems >> 3)
                                             : (feat_elems >> 2);
    const long long chunk = (Wfeat + blocks - 1) / blocks; // contiguous slice

    fused_all_kernel<<<blocks, threads>>>(
        verts_logit, verts_features, boundary, faces, (float*)d_out,
        V, faces_elems, feat_elems, feat_mode, chunk);
}

// round 7
// speedup vs baseline: 1.1920x; 1.1920x over previous
#include <cuda_runtime.h>
#include <cuda_bf16.h>

// Output layout (flattened f32 concat of the reference tuple):
//   [0, 3V)                      verts_3d   (V x 3)
//   [3V, 3V + Fe)                faces cast to f32 (Fe = in_sizes[3])
//   [3V + Fe, 3V + Fe + V*D)     verts_features copy
//
// Flat interleaved work-item space (proven best shape), ordered:
//   [0, Wfaces)                faces int->float, 4 elems/item
//   [Wfaces, +V)               verts_3d, 1 vertex/item
//   [Wfaces+V, +Wfeat)         features copy (v8 = 32B/item when aligned)
// Small regions first: absorbed in the first loop iterations, no tail.
// Exact single resident wave: 1184 blocks x 256 threads (8 blocks/SM).

__global__ void __launch_bounds__(256, 8) fused_all_kernel(
    const float* __restrict__ verts_logit,
    const float* __restrict__ verts_features,
    const float* __restrict__ boundary,
    const int*   __restrict__ faces,
    float* __restrict__ out,
    int V, int faces_elems, int feat_elems,
    int feat_mode)          // 2 = v8, 1 = v4, 0 = v4 load + scalar stores
{
    float* __restrict__ out_faces    = out + 3 * (long long)V;
    float* __restrict__ out_features = out_faces + faces_elems;

    const int Wfaces = (faces_elems + 3) >> 2;
    const int Wsmall = Wfaces + V;
    const int Wfeat  = (feat_mode == 2) ? (feat_elems >> 3)
                                        : (feat_elems >> 2);
    const int total  = Wsmall + Wfeat;

    const int S = gridDim.x * blockDim.x;
    for (int idx = blockIdx.x * blockDim.x + threadIdx.x;
         idx < total; idx += S) {
        if (idx >= Wsmall) {
            // ---- features copy (dominant) ----
            const int i = idx - Wsmall;
            if (feat_mode == 2) {
                const float* s = verts_features + ((long long)i << 3);
                float*       d = out_features   + ((long long)i << 3);
                float a0, a1, a2, a3, a4, a5, a6, a7;
                asm volatile(
                    "ld.global.nc.v8.f32 {%0,%1,%2,%3,%4,%5,%6,%7}, [%8];"
                    : "=f"(a0), "=f"(a1), "=f"(a2), "=f"(a3),
                      "=f"(a4), "=f"(a5), "=f"(a6), "=f"(a7)
                    : "l"(s));
                asm volatile(
                    "st.global.v8.f32 [%0], {%1,%2,%3,%4,%5,%6,%7,%8};"
                    :: "l"(d),
                       "f"(a0), "f"(a1), "f"(a2), "f"(a3),
                       "f"(a4), "f"(a5), "f"(a6), "f"(a7)
                    : "memory");
            } else if (feat_mode == 1) {
                const float4 v = __ldg((const float4*)verts_features + i);
                ((float4*)out_features)[i] = v;
            } else {
                const float4 v = __ldg((const float4*)verts_features + i);
                float* d = out_features + ((long long)i << 2);
                d[0] = v.x; d[1] = v.y; d[2] = v.z; d[3] = v.w;
            }
        } else if (idx < Wfaces) {
            // ---- faces int32 -> float32, 4 elems/item ----
            const int e = idx << 2;
            if (e + 4 <= faces_elems) {
                const int4 f = __ldg((const int4*)faces + idx);
                float4 o;
                o.x = (float)f.x; o.y = (float)f.y;
                o.z = (float)f.z; o.w = (float)f.w;
                ((float4*)out_faces)[idx] = o;      // offset 3V %4 == 0
            } else {
                for (int k = e; k < faces_elems; k++)
                    out_faces[k] = (float)__ldg(faces + k);
            }
        } else {
            // ---- verts_3d: sigmoid(logit)*2-1 (rows 0..3 = boundary) ----
            const int i = idx - Wfaces;
            float x, y;
            if (i < 4) {
                x = boundary[2 * i];
                y = boundary[2 * i + 1];
            } else {
                const float2 l = __ldg((const float2*)verts_logit + i);
                x = 2.0f / (1.0f + __expf(-l.x)) - 1.0f;
                y = 2.0f / (1.0f + __expf(-l.y)) - 1.0f;
            }
            float* d = out + 3 * (long long)i;
            d[0] = x; d[1] = y; d[2] = 1.0f;
        }
    }
}

extern "C" void kernel_launch(void* const* d_in, const int* in_sizes, int n_in,
                              void* d_out, int out_size) {
    const float* verts_logit    = (const float*)d_in[0];   // V*2
    const float* verts_features = (const float*)d_in[1];   // V*D
    const float* boundary       = (const float*)d_in[2];   // 4*2
    const int*   faces          = (const int*)d_in[3];     // F*3 (int32)

    const int V           = in_sizes[0] / 2;
    const int feat_elems  = in_sizes[1];                   // V*128, %8 == 0
    const int faces_elems = in_sizes[3];

    const long long off = 3LL * V + faces_elems;           // dst slice offset
    int feat_mode;
    if ((off & 7) == 0)      feat_mode = 2;                // 32B aligned: v8
    else if ((off & 3) == 0) feat_mode = 1;                // 16B aligned: v4
    else                     feat_mode = 0;                // scalar stores

    const int threads = 256;
    int blocks = 148 * 8;                                  // one exact wave
    const int Wfeat = (feat_mode == 2) ? (feat_elems >> 3)
                                       : (feat_elems >> 2);
    const long long total = (long long)((faces_elems + 3) >> 2) + V + Wfeat;
    const long long need = (total + threads - 1) / threads;
    if (need < blocks) blocks = (int)need;
    if (blocks < 1) blocks = 1;

    fused_all_kernel<<<blocks, threads>>>(
        verts_logit, verts_features, boundary, faces, (float*)d_out,
        V, faces_elems, feat_elems, feat_mode);
}